// round 5
// baseline (speedup 1.0000x reference)
#include <cuda_runtime.h>
#include <math.h>

#define NB 2
#define NA 5
#define NC 64
#define NH 128
#define NW 128
#define HW (NH*NW)
#define NAG (NB*NA)   /* 10 */

// Scratch (allocation-free rule: __device__ globals)
__device__ float g_mean[NAG*NC*HW];    // 41.9 MB
__device__ float g_feat[NAG*NC*HW];    // 41.9 MB  (iter-1 output)
__device__ float g_y[NAG*192*HW];      // 125.8 MB (conv pre-activation)
__device__ float g_wt[128*9*192];      // transposed weights [cin][tap][co]

// ---------------- packed f32x2 helpers ----------------
__device__ __forceinline__ unsigned long long pack2(float a) {
    unsigned long long r;
    unsigned int u = __float_as_uint(a);
    asm("mov.b64 %0, {%1, %1};" : "=l"(r) : "r"(u));
    return r;
}
#define FMA2(acc, a, b) asm("fma.rn.f32x2 %0, %1, %2, %0;" : "+l"(acc) : "l"(a), "l"(b))

// ---------------- weight transpose ----------------
// g_wt[(cin*9+tap)*192 + co] = wx[(co*128+cin)*9 + tap]
__global__ void wtrans_kernel(const float* __restrict__ wx) {
    int idx = blockIdx.x*blockDim.x + threadIdx.x;
    if (idx >= 192*128*9) return;
    int co = idx % 192;
    int r  = idx / 192;       // cin*9 + tap
    g_wt[r*192 + co] = wx[(co*128 + (r/9))*9 + (r % 9)];
}

// ---------------- warp + masked mean ----------------
// Fuses the two grid_samples of warp_one: pass-2 is a constant translation,
// so each output pixel needs <=16 taps of feats[b,j] with exact reference
// validity (zero padding, float-compare bounds) and clamped gather indices.
// thread = (pixel, 16-channel quarter); grid.y = b*A+i
__global__ void __launch_bounds__(256) warp_mean_kernel(
        const float* __restrict__ ext_feats, const float* __restrict__ trans,
        int use_internal) {
    const float* feats = use_internal ? g_feat : ext_feats;
    int g   = blockIdx.x * blockDim.x + threadIdx.x;   // 0..65535
    int bi  = blockIdx.y;                              // 0..9
    int pix = g & (HW - 1);
    int cq  = g >> 14;                                 // 0..3
    int b = bi / NA, i = bi % NA;
    int h = pix >> 7, w = pix & 127;

    float acc[16];
#pragma unroll
    for (int c = 0; c < 16; c++) acc[c] = 0.f;

    for (int j = 0; j < NA; j++) {
        if (j == i) continue;
        const float* t = trans + (((b*NA + i)*NA) + j)*16;
        float t00 = t[0], t01 = t[1], t03 = t[3];
        float t10 = t[4], t11 = t[5], t13 = t[7];
        float x_tr = (4.f*t03)*(1.f/128.f);
        float y_tr = -(4.f*t13)*(1.f/128.f);
        // pass-2 sample position (translation grid), mirroring reference ops
        float xsw = (float)(2*w + 1)*(1.f/128.f) - 1.f;
        float ysh = (float)(2*h + 1)*(1.f/128.f) - 1.f;
        float qx = ((xsw + x_tr + 1.f)*128.f - 1.f)*0.5f;
        float qy = ((ysh + y_tr + 1.f)*128.f - 1.f)*0.5f;
        float cx = floorf(qx), cy = floorf(qy);
        float fx = qx - cx,  fy = qy - cy;
        float w2x[2] = {1.f - fx, fx};
        float w2y[2] = {1.f - fy, fy};

        float wgt[16]; int off[16];
#pragma unroll
        for (int tt = 0; tt < 2; tt++) {
#pragma unroll
            for (int ss = 0; ss < 2; ss++) {
                float xi = cx + (float)ss, yi = cy + (float)tt;
                bool v2 = (xi >= 0.f) & (xi <= 127.f) & (yi >= 0.f) & (yi <= 127.f);
                float w2 = v2 ? w2x[ss]*w2y[tt] : 0.f;
                int q = min(max((int)xi, 0), 127);
                int p = min(max((int)yi, 0), 127);
                // pass-1 rotation sample at intermediate pixel (p,q)
                float xsq = (float)(2*q + 1)*(1.f/128.f) - 1.f;
                float ysp = (float)(2*p + 1)*(1.f/128.f) - 1.f;
                float gx = t00*xsq + t01*ysp;
                float gy = t10*xsq + t11*ysp;
                float px = ((gx + 1.f)*128.f - 1.f)*0.5f;
                float py = ((gy + 1.f)*128.f - 1.f)*0.5f;
                float rx = floorf(px), ry = floorf(py);
                float fx1 = px - rx, fy1 = py - ry;
                float w1x[2] = {1.f - fx1, fx1};
                float w1y[2] = {1.f - fy1, fy1};
#pragma unroll
                for (int v = 0; v < 2; v++) {
#pragma unroll
                    for (int u = 0; u < 2; u++) {
                        float xj = rx + (float)u, yj = ry + (float)v;
                        bool v1 = (xj >= 0.f) & (xj <= 127.f) & (yj >= 0.f) & (yj <= 127.f);
                        float w1 = v1 ? w1x[u]*w1y[v] : 0.f;
                        int xc = min(max((int)xj, 0), 127);
                        int yc = min(max((int)yj, 0), 127);
                        int k = (tt*2 + ss)*4 + v*2 + u;
                        wgt[k] = w2*w1;
                        off[k] = yc*NW + xc;
                    }
                }
            }
        }
        const float* fj = feats + (((b*NA + j)*NC) + cq*16)*HW;
#pragma unroll
        for (int c = 0; c < 16; c++) {
            const float* fc = fj + c*HW;
            float s = 0.f;
#pragma unroll
            for (int k = 0; k < 16; k++) s += wgt[k]*fc[off[k]];
            acc[c] += s;
        }
    }
    float* mout = g_mean + (bi*NC + cq*16)*HW + pix;
#pragma unroll
    for (int c = 0; c < 16; c++) mout[c*HW] = acc[c]*0.25f;
}

// ---------------- 3x3 conv (input = concat(feats, mean), 128 cin -> 192 co)
// Implicit-GEMM style: block tile = 64 px (one row segment) x 64 co,
// 128 threads, thread tile = 4 px x 8 co accumulated as packed f32x2 pairs.
__global__ void __launch_bounds__(128) conv_kernel(
        const float* __restrict__ ext_feats, int use_internal) {
    const float* fin = use_internal ? g_feat : ext_feats;
    int x0 = blockIdx.x * 64;            // 0 or 64
    int y  = blockIdx.y;                 // 0..127
    int n  = blockIdx.z / 3;             // 0..9
    int cot = blockIdx.z % 3;            // 0..2
    int co0 = cot*64;

    __shared__ float in_s[8][3][68];     // 8 cin x 3 rows x (64+2 pad, stride 68 for 16B align)
    __shared__ float w_s[8*9*64];        // [ci][tap][co]

    int tid  = threadIdx.x;
    int co_t = tid & 7;                  // 8 co-threads * 8 co
    int px_t = tid >> 3;                 // 16 px-threads * 4 px
    int pxl  = px_t*4;

    unsigned long long acc[4][4];        // [px][co-pair]
#pragma unroll
    for (int a = 0; a < 4; a++)
#pragma unroll
        for (int c2 = 0; c2 < 4; c2++) acc[a][c2] = 0ull;

    for (int cin0 = 0; cin0 < 128; cin0 += 8) {
        __syncthreads();
        // stage input tile (zero-padded SAME borders)
        for (int idx = tid; idx < 8*3*68; idx += 128) {
            int ci = idx / 204; int r = idx - ci*204;
            int ky = r / 68;    int col = r - ky*68;
            int gxp = x0 - 1 + col, gyp = y - 1 + ky;
            float v = 0.f;
            int ch = cin0 + ci;
            if (col < 66 && (unsigned)gxp < 128u && (unsigned)gyp < 128u) {
                const float* src = (ch < 64) ? fin : g_mean;
                v = src[((n*NC + (ch & 63))*NH + gyp)*NW + gxp];
            }
            in_s[ci][ky][col] = v;
        }
        // stage weights (coalesced from transposed layout)
        for (int idx = tid; idx < 8*9*64; idx += 128) {
            int ci = idx / 576; int r = idx - ci*576;
            int tap = r >> 6;   int col = r & 63;
            w_s[idx] = g_wt[((cin0 + ci)*9 + tap)*192 + co0 + col];
        }
        __syncthreads();

        for (int ci = 0; ci < 8; ci++) {   // rolled: keeps body in I$ L0
#pragma unroll
            for (int ky = 0; ky < 3; ky++) {
                float4 va = *(const float4*)&in_s[ci][ky][pxl];
                float4 vb = *(const float4*)&in_s[ci][ky][pxl + 4];
                float v[8] = {va.x, va.y, va.z, va.w, vb.x, vb.y, vb.z, vb.w};
#pragma unroll
                for (int kx = 0; kx < 3; kx++) {
                    const unsigned long long* wp =
                        (const unsigned long long*)&w_s[(ci*9 + ky*3 + kx)*64 + co_t*8];
                    unsigned long long b0 = wp[0], b1 = wp[1], b2 = wp[2], b3 = wp[3];
                    unsigned long long a0 = pack2(v[kx + 0]);
                    unsigned long long a1 = pack2(v[kx + 1]);
                    unsigned long long a2 = pack2(v[kx + 2]);
                    unsigned long long a3 = pack2(v[kx + 3]);
                    FMA2(acc[0][0], a0, b0); FMA2(acc[0][1], a0, b1);
                    FMA2(acc[0][2], a0, b2); FMA2(acc[0][3], a0, b3);
                    FMA2(acc[1][0], a1, b0); FMA2(acc[1][1], a1, b1);
                    FMA2(acc[1][2], a1, b2); FMA2(acc[1][3], a1, b3);
                    FMA2(acc[2][0], a2, b0); FMA2(acc[2][1], a2, b1);
                    FMA2(acc[2][2], a2, b2); FMA2(acc[2][3], a2, b3);
                    FMA2(acc[3][0], a3, b0); FMA2(acc[3][1], a3, b1);
                    FMA2(acc[3][2], a3, b2); FMA2(acc[3][3], a3, b3);
                }
            }
        }
    }
    // write pre-activations to g_y (vectorized: 4 px per STG.128)
    int pixbase = y*NW + x0 + pxl;
#pragma unroll
    for (int cp = 0; cp < 4; cp++) {
        float4 lo, hi;
        lo.x = __uint_as_float((unsigned)acc[0][cp]); hi.x = __uint_as_float((unsigned)(acc[0][cp] >> 32));
        lo.y = __uint_as_float((unsigned)acc[1][cp]); hi.y = __uint_as_float((unsigned)(acc[1][cp] >> 32));
        lo.z = __uint_as_float((unsigned)acc[2][cp]); hi.z = __uint_as_float((unsigned)(acc[2][cp] >> 32));
        lo.w = __uint_as_float((unsigned)acc[3][cp]); hi.w = __uint_as_float((unsigned)(acc[3][cp] >> 32));
        int cobase = co0 + co_t*8 + cp*2;
        *(float4*)&g_y[(n*192 + cobase    )*HW + pixbase] = lo;
        *(float4*)&g_y[(n*192 + cobase + 1)*HW + pixbase] = hi;
    }
}

// ---------------- fused GRU epilogue (h0 = 0) ----------------
// r = sig(yr + bx_r + bh_r); z = sig(yz + bx_z + bh_z);
// n = tanh(yn + bx_n + r*bh_n); out = (1-z)*n
__global__ void __launch_bounds__(256) gru_kernel(
        const float* __restrict__ bx, const float* __restrict__ bh,
        float* __restrict__ ext_out, int to_internal) {
    float* dst = to_internal ? g_feat : ext_out;
    int idx = blockIdx.x*blockDim.x + threadIdx.x;     // over 10*64*HW
    if (idx >= NAG*NC*HW) return;
    int pix = idx & (HW - 1);
    int c   = (idx >> 14) & 63;
    int n   = idx >> 20;
    const float* yb = g_y + n*192*HW;
    float yr = yb[(c      )*HW + pix] + bx[c      ] + bh[c      ];
    float yz = yb[(64  + c)*HW + pix] + bx[64  + c] + bh[64  + c];
    float r = 1.f/(1.f + expf(-yr));
    float z = 1.f/(1.f + expf(-yz));
    float yn = yb[(128 + c)*HW + pix] + bx[128 + c] + r*bh[128 + c];
    float nn = tanhf(yn);
    dst[idx] = (1.f - z)*nn;
}

// ---------------- launch ----------------
extern "C" void kernel_launch(void* const* d_in, const int* in_sizes, int n_in,
                              void* d_out, int out_size) {
    const float* feats = (const float*)d_in[0];
    const float* trans = (const float*)d_in[1];
    const float* wx    = (const float*)d_in[2];
    // d_in[3] = wh (unused: h0 = 0), d_in[6]/d_in[7] = scalars (fixed by setup)
    const float* bx    = (const float*)d_in[4];
    const float* bh    = (const float*)d_in[5];
    float* out = (float*)d_out;

    wtrans_kernel<<<(192*128*9 + 255)/256, 256>>>(wx);

    // iteration 1: src = external feats -> g_feat
    warp_mean_kernel<<<dim3(256, NAG), 256>>>(feats, trans, 0);
    conv_kernel<<<dim3(2, 128, NAG*3), 128>>>(feats, 0);
    gru_kernel<<<(NAG*NC*HW + 255)/256, 256>>>(bx, bh, out, 1);

    // iteration 2: src = g_feat -> d_out
    warp_mean_kernel<<<dim3(256, NAG), 256>>>(feats, trans, 1);
    conv_kernel<<<dim3(2, 128, NAG*3), 128>>>(feats, 1);
    gru_kernel<<<(NAG*NC*HW + 255)/256, 256>>>(bx, bh, out, 0);
}

// round 7
// speedup vs baseline: 1.4325x; 1.4325x over previous
#include <cuda_runtime.h>
#include <math.h>

#define NB 2
#define NA 5
#define NC 64
#define NH 128
#define NW 128
#define HW (NH*NW)
#define NAG (NB*NA)   /* 10 */

// Scratch (allocation-free rule: __device__ globals)
__device__ float g_mean[NAG*NC*HW];    // 41.9 MB
__device__ float g_feat[NAG*NC*HW];    // 41.9 MB  (iter-1 output)
__device__ float g_y[NAG*192*HW];      // 125.8 MB (conv pre-activation)
__device__ float g_wt[128*9*192];      // transposed weights [cin][tap][co]

// ---------------- packed f32x2 helpers ----------------
__device__ __forceinline__ unsigned long long pack2(float a) {
    unsigned long long r;
    unsigned int u = __float_as_uint(a);
    asm("mov.b64 %0, {%1, %1};" : "=l"(r) : "r"(u));
    return r;
}
#define FMA2(acc, a, b) asm("fma.rn.f32x2 %0, %1, %2, %0;" : "+l"(acc) : "l"(a), "l"(b))

// ---------------- weight transpose ----------------
// g_wt[(cin*9+tap)*192 + co] = wx[(co*128+cin)*9 + tap]
__global__ void wtrans_kernel(const float* __restrict__ wx) {
    int idx = blockIdx.x*blockDim.x + threadIdx.x;
    if (idx >= 192*128*9) return;
    int co = idx % 192;
    int r  = idx / 192;       // cin*9 + tap
    g_wt[r*192 + co] = wx[(co*128 + (r/9))*9 + (r % 9)];
}

// ---------------- warp + masked mean ----------------
// Fuses the two grid_samples of warp_one: pass-2 is a constant translation,
// so each output pixel needs <=16 taps of feats[b,j] with exact reference
// validity (zero padding, float-compare bounds) and clamped gather indices.
// thread = (pixel, 16-channel quarter); grid.y = b*A+i
__global__ void __launch_bounds__(256) warp_mean_kernel(
        const float* __restrict__ ext_feats, const float* __restrict__ trans,
        int use_internal) {
    const float* feats = use_internal ? g_feat : ext_feats;
    int g   = blockIdx.x * blockDim.x + threadIdx.x;   // 0..65535
    int bi  = blockIdx.y;                              // 0..9
    int pix = g & (HW - 1);
    int cq  = g >> 14;                                 // 0..3
    int b = bi / NA, i = bi % NA;
    int h = pix >> 7, w = pix & 127;

    float acc[16];
#pragma unroll
    for (int c = 0; c < 16; c++) acc[c] = 0.f;

    for (int j = 0; j < NA; j++) {
        if (j == i) continue;
        const float* t = trans + (((b*NA + i)*NA) + j)*16;
        float t00 = t[0], t01 = t[1], t03 = t[3];
        float t10 = t[4], t11 = t[5], t13 = t[7];
        float x_tr = (4.f*t03)*(1.f/128.f);
        float y_tr = -(4.f*t13)*(1.f/128.f);
        // pass-2 sample position (translation grid), mirroring reference ops
        float xsw = (float)(2*w + 1)*(1.f/128.f) - 1.f;
        float ysh = (float)(2*h + 1)*(1.f/128.f) - 1.f;
        float qx = ((xsw + x_tr + 1.f)*128.f - 1.f)*0.5f;
        float qy = ((ysh + y_tr + 1.f)*128.f - 1.f)*0.5f;
        float cx = floorf(qx), cy = floorf(qy);
        float fx = qx - cx,  fy = qy - cy;
        float w2x[2] = {1.f - fx, fx};
        float w2y[2] = {1.f - fy, fy};

        float wgt[16]; int off[16];
#pragma unroll
        for (int tt = 0; tt < 2; tt++) {
#pragma unroll
            for (int ss = 0; ss < 2; ss++) {
                float xi = cx + (float)ss, yi = cy + (float)tt;
                bool v2 = (xi >= 0.f) & (xi <= 127.f) & (yi >= 0.f) & (yi <= 127.f);
                float w2 = v2 ? w2x[ss]*w2y[tt] : 0.f;
                int q = min(max((int)xi, 0), 127);
                int p = min(max((int)yi, 0), 127);
                // pass-1 rotation sample at intermediate pixel (p,q)
                float xsq = (float)(2*q + 1)*(1.f/128.f) - 1.f;
                float ysp = (float)(2*p + 1)*(1.f/128.f) - 1.f;
                float gx = t00*xsq + t01*ysp;
                float gy = t10*xsq + t11*ysp;
                float px = ((gx + 1.f)*128.f - 1.f)*0.5f;
                float py = ((gy + 1.f)*128.f - 1.f)*0.5f;
                float rx = floorf(px), ry = floorf(py);
                float fx1 = px - rx, fy1 = py - ry;
                float w1x[2] = {1.f - fx1, fx1};
                float w1y[2] = {1.f - fy1, fy1};
#pragma unroll
                for (int v = 0; v < 2; v++) {
#pragma unroll
                    for (int u = 0; u < 2; u++) {
                        float xj = rx + (float)u, yj = ry + (float)v;
                        bool v1 = (xj >= 0.f) & (xj <= 127.f) & (yj >= 0.f) & (yj <= 127.f);
                        float w1 = v1 ? w1x[u]*w1y[v] : 0.f;
                        int xc = min(max((int)xj, 0), 127);
                        int yc = min(max((int)yj, 0), 127);
                        int k = (tt*2 + ss)*4 + v*2 + u;
                        wgt[k] = w2*w1;
                        off[k] = yc*NW + xc;
                    }
                }
            }
        }
        const float* fj = feats + (((b*NA + j)*NC) + cq*16)*HW;
#pragma unroll
        for (int c = 0; c < 16; c++) {
            const float* fc = fj + c*HW;
            float s = 0.f;
#pragma unroll
            for (int k = 0; k < 16; k++) s += wgt[k]*fc[off[k]];
            acc[c] += s;
        }
    }
    float* mout = g_mean + (bi*NC + cq*16)*HW + pix;
#pragma unroll
    for (int c = 0; c < 16; c++) mout[c*HW] = acc[c]*0.25f;
}

// ---------------- 3x3 conv (input = concat(feats, mean), 128 cin -> 192 co)
// Implicit-GEMM style: block tile = 128 px (one full row) x 64 co,
// 128 threads, thread tile = 8 px x 8 co accumulated as packed f32x2 pairs.
// smem bytes/FMA = 0.71 -> ~91 B/cyc/SM at full fma rate (< 128 crossbar cap).
__global__ void __launch_bounds__(128, 4) conv_kernel(
        const float* __restrict__ ext_feats, int use_internal) {
    const float* fin = use_internal ? g_feat : ext_feats;
    int y   = blockIdx.x;                // 0..127
    int n   = blockIdx.y / 3;            // 0..9
    int cot = blockIdx.y % 3;            // 0..2
    int co0 = cot*64;

    __shared__ float in_s[8][3][132];    // 8 cin x 3 rows x (128+2 pad, stride 132)
    __shared__ float w_s[8*9*64];        // [ci][tap][co]

    int tid  = threadIdx.x;
    int co_t = tid & 7;                  // 8 co-threads * 8 co
    int px_t = tid >> 3;                 // 16 px-threads * 8 px
    int pxl  = px_t*8;

    unsigned long long acc[8][4];        // [px][co-pair]
#pragma unroll
    for (int a = 0; a < 8; a++)
#pragma unroll
        for (int c2 = 0; c2 < 4; c2++) acc[a][c2] = 0ull;

    for (int cin0 = 0; cin0 < 128; cin0 += 8) {
        __syncthreads();
        // stage input tile (zero-padded SAME borders), full 128-px row + halo
        for (int idx = tid; idx < 8*3*132; idx += 128) {
            int ci = idx / 396; int r = idx - ci*396;
            int ky = r / 132;   int col = r - ky*132;
            int gxp = col - 1, gyp = y - 1 + ky;
            float v = 0.f;
            int ch = cin0 + ci;
            if ((unsigned)gxp < 128u && (unsigned)gyp < 128u) {
                const float* src = (ch < 64) ? fin : g_mean;
                v = src[((n*NC + (ch & 63))*NH + gyp)*NW + gxp];
            }
            in_s[ci][ky][col] = v;
        }
        // stage weights, vectorized float4 (both sides 16B aligned)
        for (int idx = tid; idx < 8*9*16; idx += 128) {
            int ci = idx / 144; int r = idx - ci*144;
            int tap = r >> 4;   int c4 = r & 15;
            *(float4*)&w_s[(ci*9 + tap)*64 + c4*4] =
                *(const float4*)&g_wt[((cin0 + ci)*9 + tap)*192 + co0 + c4*4];
        }
        __syncthreads();

        for (int ci = 0; ci < 8; ci++) {   // rolled: keeps body in I$ L0
#pragma unroll
            for (int ky = 0; ky < 3; ky++) {
                float4 va = *(const float4*)&in_s[ci][ky][pxl];
                float4 vb = *(const float4*)&in_s[ci][ky][pxl + 4];
                float2 vc = *(const float2*)&in_s[ci][ky][pxl + 8];
                unsigned long long av[10];
                av[0] = pack2(va.x); av[1] = pack2(va.y);
                av[2] = pack2(va.z); av[3] = pack2(va.w);
                av[4] = pack2(vb.x); av[5] = pack2(vb.y);
                av[6] = pack2(vb.z); av[7] = pack2(vb.w);
                av[8] = pack2(vc.x); av[9] = pack2(vc.y);
#pragma unroll
                for (int kx = 0; kx < 3; kx++) {
                    const unsigned long long* wp =
                        (const unsigned long long*)&w_s[(ci*9 + ky*3 + kx)*64 + co_t*8];
                    unsigned long long b0 = wp[0], b1 = wp[1], b2 = wp[2], b3 = wp[3];
#pragma unroll
                    for (int p = 0; p < 8; p++) {
                        FMA2(acc[p][0], av[kx + p], b0);
                        FMA2(acc[p][1], av[kx + p], b1);
                        FMA2(acc[p][2], av[kx + p], b2);
                        FMA2(acc[p][3], av[kx + p], b3);
                    }
                }
            }
        }
    }
    // write pre-activations to g_y (vectorized: 4 px per STG.128)
    int pixbase = y*NW + pxl;
#pragma unroll
    for (int cp = 0; cp < 4; cp++) {
        float4 lo0, lo1, hi0, hi1;
        lo0.x = __uint_as_float((unsigned)acc[0][cp]); hi0.x = __uint_as_float((unsigned)(acc[0][cp] >> 32));
        lo0.y = __uint_as_float((unsigned)acc[1][cp]); hi0.y = __uint_as_float((unsigned)(acc[1][cp] >> 32));
        lo0.z = __uint_as_float((unsigned)acc[2][cp]); hi0.z = __uint_as_float((unsigned)(acc[2][cp] >> 32));
        lo0.w = __uint_as_float((unsigned)acc[3][cp]); hi0.w = __uint_as_float((unsigned)(acc[3][cp] >> 32));
        lo1.x = __uint_as_float((unsigned)acc[4][cp]); hi1.x = __uint_as_float((unsigned)(acc[4][cp] >> 32));
        lo1.y = __uint_as_float((unsigned)acc[5][cp]); hi1.y = __uint_as_float((unsigned)(acc[5][cp] >> 32));
        lo1.z = __uint_as_float((unsigned)acc[6][cp]); hi1.z = __uint_as_float((unsigned)(acc[6][cp] >> 32));
        lo1.w = __uint_as_float((unsigned)acc[7][cp]); hi1.w = __uint_as_float((unsigned)(acc[7][cp] >> 32));
        int cobase = co0 + co_t*8 + cp*2;
        float* base0 = &g_y[(n*192 + cobase    )*HW + pixbase];
        float* base1 = &g_y[(n*192 + cobase + 1)*HW + pixbase];
        *(float4*)base0       = lo0;
        *(float4*)(base0 + 4) = lo1;
        *(float4*)base1       = hi0;
        *(float4*)(base1 + 4) = hi1;
    }
}

// ---------------- fused GRU epilogue (h0 = 0), float4-vectorized ----------------
// r = sig(yr + bx_r + bh_r); z = sig(yz + bx_z + bh_z);
// n = tanh(yn + bx_n + r*bh_n); out = (1-z)*n
__global__ void __launch_bounds__(256) gru_kernel(
        const float* __restrict__ bx, const float* __restrict__ bh,
        float* __restrict__ ext_out, int to_internal) {
    float* dst = to_internal ? g_feat : ext_out;
    int idx = blockIdx.x*blockDim.x + threadIdx.x;     // over (10*64*HW)/4
    if (idx >= NAG*NC*HW/4) return;
    int e   = idx*4;
    int pix = e & (HW - 1);
    int c   = (e >> 14) & 63;
    int n   = e >> 20;
    const float* yb = g_y + n*192*HW;
    float4 yr4 = *(const float4*)&yb[(c      )*HW + pix];
    float4 yz4 = *(const float4*)&yb[(64  + c)*HW + pix];
    float4 yn4 = *(const float4*)&yb[(128 + c)*HW + pix];
    float br = bx[c] + bh[c];
    float bz = bx[64 + c] + bh[64 + c];
    float bxn = bx[128 + c], bhn = bh[128 + c];
    float4 o;
    {
        float r = 1.f/(1.f + __expf(-(yr4.x + br)));
        float z = 1.f/(1.f + __expf(-(yz4.x + bz)));
        o.x = (1.f - z)*tanhf(yn4.x + bxn + r*bhn);
    }
    {
        float r = 1.f/(1.f + __expf(-(yr4.y + br)));
        float z = 1.f/(1.f + __expf(-(yz4.y + bz)));
        o.y = (1.f - z)*tanhf(yn4.y + bxn + r*bhn);
    }
    {
        float r = 1.f/(1.f + __expf(-(yr4.z + br)));
        float z = 1.f/(1.f + __expf(-(yz4.z + bz)));
        o.z = (1.f - z)*tanhf(yn4.z + bxn + r*bhn);
    }
    {
        float r = 1.f/(1.f + __expf(-(yr4.w + br)));
        float z = 1.f/(1.f + __expf(-(yz4.w + bz)));
        o.w = (1.f - z)*tanhf(yn4.w + bxn + r*bhn);
    }
    *(float4*)&dst[e] = o;
}

// ---------------- launch ----------------
extern "C" void kernel_launch(void* const* d_in, const int* in_sizes, int n_in,
                              void* d_out, int out_size) {
    const float* feats = (const float*)d_in[0];
    const float* trans = (const float*)d_in[1];
    const float* wx    = (const float*)d_in[2];
    // d_in[3] = wh (unused: h0 = 0), d_in[6]/d_in[7] = scalars (fixed by setup)
    const float* bx    = (const float*)d_in[4];
    const float* bh    = (const float*)d_in[5];
    float* out = (float*)d_out;

    wtrans_kernel<<<(192*128*9 + 255)/256, 256>>>(wx);

    // iteration 1: src = external feats -> g_feat
    warp_mean_kernel<<<dim3(256, NAG), 256>>>(feats, trans, 0);
    conv_kernel<<<dim3(128, NAG*3), 128>>>(feats, 0);
    gru_kernel<<<(NAG*NC*HW/4 + 255)/256, 256>>>(bx, bh, out, 1);

    // iteration 2: src = g_feat -> d_out
    warp_mean_kernel<<<dim3(256, NAG), 256>>>(feats, trans, 1);
    conv_kernel<<<dim3(128, NAG*3), 128>>>(feats, 1);
    gru_kernel<<<(NAG*NC*HW/4 + 255)/256, 256>>>(bx, bh, out, 0);
}

// round 9
// speedup vs baseline: 2.5412x; 1.7740x over previous
#include <cuda_runtime.h>
#include <math.h>
#include <stdint.h>

#define NB 2
#define NA 5
#define NC 64
#define NH 128
#define NW 128
#define HW (NH*NW)
#define NAG (NB*NA)   /* 10 */

// Scratch (allocation-free rule: __device__ globals)
__device__ float    g_mean[NAG*NC*HW];      // 41.9 MB
__device__ float    g_feat[NAG*NC*HW];      // 41.9 MB  (iter-1 output)
__device__ float    g_yt[NAG*HW*192];       // 125.8 MB conv pre-activation, [n][pix][co]
__device__ uint32_t g_wt3[3*8*2*3*16*96];   // tf32 weights [ky][cc][half][kx][ci16][co96]

// ---------------- mma.sync tf32 helpers (sm_80 ISA -> compiles at compute_103) ----
__device__ __forceinline__ uint32_t cvt_tf32(float x) {
    uint32_t r; asm("cvt.rna.tf32.f32 %0, %1;" : "=r"(r) : "f"(x)); return r;
}
__device__ __forceinline__ void mma_tf32(float* d, const uint32_t* a, const uint32_t* b) {
    asm volatile("mma.sync.aligned.m16n8k8.row.col.f32.tf32.tf32.f32 "
        "{%0,%1,%2,%3}, {%4,%5,%6,%7}, {%8,%9}, {%0,%1,%2,%3};"
        : "+f"(d[0]), "+f"(d[1]), "+f"(d[2]), "+f"(d[3])
        : "r"(a[0]), "r"(a[1]), "r"(a[2]), "r"(a[3]), "r"(b[0]), "r"(b[1]));
}

// ---------------- weight prep: tf32-convert + reorder ----------------
// g_wt3 linear index = [ky][cc][half][kx][ci16][co96] (co fastest)
__global__ void wtrans3_kernel(const float* __restrict__ wx) {
    int idx = blockIdx.x*blockDim.x + threadIdx.x;
    if (idx >= 3*8*2*3*16*96) return;
    int co   = idx % 96;
    int ci   = (idx / 96) % 16;
    int kx   = (idx / (96*16)) % 3;
    int half = (idx / (96*16*3)) % 2;
    int cc   = (idx / (96*16*3*2)) % 8;
    int ky   = idx / (96*16*3*2*8);
    float v = wx[((half*96 + co)*128 + cc*16 + ci)*9 + ky*3 + kx];
    g_wt3[idx] = cvt_tf32(v);
}

// ---------------- warp + masked mean (proven) ----------------
__global__ void __launch_bounds__(256) warp_mean_kernel(
        const float* __restrict__ ext_feats, const float* __restrict__ trans,
        int use_internal) {
    const float* feats = use_internal ? g_feat : ext_feats;
    int g   = blockIdx.x * blockDim.x + threadIdx.x;
    int bi  = blockIdx.y;
    int pix = g & (HW - 1);
    int cq  = g >> 14;
    int b = bi / NA, i = bi % NA;
    int h = pix >> 7, w = pix & 127;

    float acc[16];
#pragma unroll
    for (int c = 0; c < 16; c++) acc[c] = 0.f;

    for (int j = 0; j < NA; j++) {
        if (j == i) continue;
        const float* t = trans + (((b*NA + i)*NA) + j)*16;
        float t00 = t[0], t01 = t[1], t03 = t[3];
        float t10 = t[4], t11 = t[5], t13 = t[7];
        float x_tr = (4.f*t03)*(1.f/128.f);
        float y_tr = -(4.f*t13)*(1.f/128.f);
        float xsw = (float)(2*w + 1)*(1.f/128.f) - 1.f;
        float ysh = (float)(2*h + 1)*(1.f/128.f) - 1.f;
        float qx = ((xsw + x_tr + 1.f)*128.f - 1.f)*0.5f;
        float qy = ((ysh + y_tr + 1.f)*128.f - 1.f)*0.5f;
        float cx = floorf(qx), cy = floorf(qy);
        float fx = qx - cx,  fy = qy - cy;
        float w2x[2] = {1.f - fx, fx};
        float w2y[2] = {1.f - fy, fy};

        float wgt[16]; int off[16];
#pragma unroll
        for (int tt = 0; tt < 2; tt++) {
#pragma unroll
            for (int ss = 0; ss < 2; ss++) {
                float xi = cx + (float)ss, yi = cy + (float)tt;
                bool v2 = (xi >= 0.f) & (xi <= 127.f) & (yi >= 0.f) & (yi <= 127.f);
                float w2 = v2 ? w2x[ss]*w2y[tt] : 0.f;
                int q = min(max((int)xi, 0), 127);
                int p = min(max((int)yi, 0), 127);
                float xsq = (float)(2*q + 1)*(1.f/128.f) - 1.f;
                float ysp = (float)(2*p + 1)*(1.f/128.f) - 1.f;
                float gx = t00*xsq + t01*ysp;
                float gy = t10*xsq + t11*ysp;
                float px = ((gx + 1.f)*128.f - 1.f)*0.5f;
                float py = ((gy + 1.f)*128.f - 1.f)*0.5f;
                float rx = floorf(px), ry = floorf(py);
                float fx1 = px - rx, fy1 = py - ry;
                float w1x[2] = {1.f - fx1, fx1};
                float w1y[2] = {1.f - fy1, fy1};
#pragma unroll
                for (int v = 0; v < 2; v++) {
#pragma unroll
                    for (int u = 0; u < 2; u++) {
                        float xj = rx + (float)u, yj = ry + (float)v;
                        bool v1 = (xj >= 0.f) & (xj <= 127.f) & (yj >= 0.f) & (yj <= 127.f);
                        float w1 = v1 ? w1x[u]*w1y[v] : 0.f;
                        int xc = min(max((int)xj, 0), 127);
                        int yc = min(max((int)yj, 0), 127);
                        int k = (tt*2 + ss)*4 + v*2 + u;
                        wgt[k] = w2*w1;
                        off[k] = yc*NW + xc;
                    }
                }
            }
        }
        const float* fj = feats + (((b*NA + j)*NC) + cq*16)*HW;
#pragma unroll
        for (int c = 0; c < 16; c++) {
            const float* fc = fj + c*HW;
            float s = 0.f;
#pragma unroll
            for (int k = 0; k < 16; k++) s += wgt[k]*fc[off[k]];
            acc[c] += s;
        }
    }
    float* mout = g_mean + (bi*NC + cq*16)*HW + pix;
#pragma unroll
    for (int c = 0; c < 16; c++) mout[c*HW] = acc[c]*0.25f;
}

// ---------------- tf32 mma.sync conv ----------------
// Block = (y-pair, co-half 96, agent). M=256 (2 rows x 128 px), N=96, K=1152.
// kx shift folded into A-fragment loads from haloed row buffer.
// Warp tile 64x48 (4 mtiles x 6 ntiles of m16n8k8). 8 warps: 4m x 2n.
#define XS_ROW 136
#define XS_RSZ (16*XS_ROW)        /* per input row: 16 ci x 136 */
#define WS_ROW 104

__global__ void __launch_bounds__(256) conv_mma_kernel(
        const float* __restrict__ ext_feats, int use_internal) {
    const float* fin = use_internal ? g_feat : ext_feats;
    __shared__ float    xs[2*XS_RSZ];      // [row2][ci16][136]  17.4 KB
    __shared__ uint32_t ws[3*16*WS_ROW];   // [kx3][ci16][co pad104] 20 KB

    int y0   = blockIdx.x*2;     // output rows y0, y0+1
    int half = blockIdx.y;       // co half (96 each)
    int n    = blockIdx.z;       // agent
    int tid  = threadIdx.x;
    int lane = tid & 31;
    int wid  = tid >> 5;
    int g    = lane >> 2, tig = lane & 3;
    int wm   = wid & 3,  wn  = wid >> 2;
    int xb   = (wm & 1)*64;
    int rowsel = wm >> 1;

    float acc[4][6][4];
#pragma unroll
    for (int mt = 0; mt < 4; mt++)
#pragma unroll
        for (int nt = 0; nt < 6; nt++)
#pragma unroll
            for (int q = 0; q < 4; q++) acc[mt][nt][q] = 0.f;

    for (int ky = 0; ky < 3; ky++) {
        for (int cc = 0; cc < 8; cc++) {
            __syncthreads();
            // halo zeros (input x' = -1 and 128 -> smem px index 3 and 132)
            if (tid < 64) {
                int ci = tid & 15, hp = (tid >> 4) & 1, row = tid >> 5;
                xs[row*XS_RSZ + ci*XS_ROW + (hp ? 132 : 3)] = 0.f;
            }
            // stage X: rows gy = y0-1+ky+row, 16 ci, smem [row][ci][x'+4]
            for (int f = tid; f < 1024; f += 256) {
                int xg = f & 31, ci = (f >> 5) & 15, row = f >> 9;
                int gy = y0 - 1 + ky + row;
                int ch = cc*16 + ci;
                float4 v = make_float4(0.f, 0.f, 0.f, 0.f);
                if ((unsigned)gy < 128u) {
                    const float* src = (ch < 64) ? fin : g_mean;
                    v = *(const float4*)&src[((n*NC + (ch & 63))*NH + gy)*NW + xg*4];
                }
                *(float4*)&xs[row*XS_RSZ + ci*XS_ROW + xg*4 + 4] = v;
            }
            // stage W: pre-tf32 region, insert pad 96->104
            {
                int region = (ky*8 + cc)*2 + half;
                const uint4* wsrc = (const uint4*)(g_wt3 + region*4608);
                for (int f = tid; f < 1152; f += 256) {
                    int co4 = f % 24;
                    int rem = f / 24;
                    int ci  = rem & 15;
                    int kx  = rem >> 4;
                    *(uint4*)&ws[(kx*16 + ci)*WS_ROW + co4*4] = wsrc[f];
                }
            }
            __syncthreads();

#pragma unroll
            for (int kx = 0; kx < 3; kx++) {
#pragma unroll
                for (int ks = 0; ks < 2; ks++) {
                    uint32_t A[4][4];
#pragma unroll
                    for (int mt = 0; mt < 4; mt++) {
                        const float* base = &xs[rowsel*XS_RSZ + (ks*8 + tig)*XS_ROW];
                        int xi = xb + mt*16 + g + kx + 3;   // x' = x+kx-1, +4 offset
                        A[mt][0] = cvt_tf32(base[xi]);               // (g,    k=tig)
                        A[mt][1] = cvt_tf32(base[xi + 8]);           // (g+8,  k=tig)
                        A[mt][2] = cvt_tf32(base[xi + 4*XS_ROW]);    // (g,    k=tig+4)
                        A[mt][3] = cvt_tf32(base[xi + 8 + 4*XS_ROW]);// (g+8,  k=tig+4)
                    }
                    uint32_t B[6][2];
#pragma unroll
                    for (int nt = 0; nt < 6; nt++) {
                        int co = wn*48 + nt*8 + g;
                        B[nt][0] = ws[(kx*16 + ks*8 + tig    )*WS_ROW + co];
                        B[nt][1] = ws[(kx*16 + ks*8 + tig + 4)*WS_ROW + co];
                    }
#pragma unroll
                    for (int mt = 0; mt < 4; mt++)
#pragma unroll
                        for (int nt = 0; nt < 6; nt++)
                            mma_tf32(acc[mt][nt], A[mt], B[nt]);
                }
            }
        }
    }

    // epilogue: D frag (g,2tig),(g,2tig+1),(g+8,2tig),(g+8,2tig+1) -> g_yt
    int yy = y0 + rowsel;
#pragma unroll
    for (int mt = 0; mt < 4; mt++) {
        int x = xb + mt*16 + g;
#pragma unroll
        for (int nt = 0; nt < 6; nt++) {
            int cobase = half*96 + wn*48 + nt*8 + tig*2;
            float* p0 = &g_yt[(size_t)(n*HW + yy*NW + x)*192 + cobase];
            *(float2*)p0 = make_float2(acc[mt][nt][0], acc[mt][nt][1]);
            float* p1 = p0 + 8*192;
            *(float2*)p1 = make_float2(acc[mt][nt][2], acc[mt][nt][3]);
        }
    }
}

// ---------------- fused GRU epilogue (h0 = 0), reads [pix][co] layout ----------
__global__ void __launch_bounds__(256) gru_kernel(
        const float* __restrict__ bx, const float* __restrict__ bh,
        float* __restrict__ ext_out, int to_internal) {
    float* dst = to_internal ? g_feat : ext_out;
    int t = blockIdx.x*blockDim.x + threadIdx.x;   // over NAG*64*(HW/4)
    if (t >= NAG*64*(HW/4)) return;
    int c  = t & 63;
    int pg = (t >> 6) & (HW/4 - 1);
    int n  = t >> 18;
    int pix = pg*4;
    float br  = bx[c] + bh[c];
    float bz  = bx[64 + c] + bh[64 + c];
    float bxn = bx[128 + c], bhn = bh[128 + c];
    const float* yb = g_yt + (size_t)(n*HW + pix)*192;
    float o[4];
#pragma unroll
    for (int p = 0; p < 4; p++) {
        float yr = yb[p*192 + c];
        float yz = yb[p*192 + 64 + c];
        float yn = yb[p*192 + 128 + c];
        float r = 1.f/(1.f + __expf(-(yr + br)));
        float z = 1.f/(1.f + __expf(-(yz + bz)));
        o[p] = (1.f - z)*tanhf(yn + bxn + r*bhn);
    }
    *(float4*)&dst[(n*NC + c)*HW + pix] = make_float4(o[0], o[1], o[2], o[3]);
}

// ---------------- launch ----------------
extern "C" void kernel_launch(void* const* d_in, const int* in_sizes, int n_in,
                              void* d_out, int out_size) {
    const float* feats = (const float*)d_in[0];
    const float* trans = (const float*)d_in[1];
    const float* wx    = (const float*)d_in[2];
    const float* bx    = (const float*)d_in[4];
    const float* bh    = (const float*)d_in[5];
    float* out = (float*)d_out;

    wtrans3_kernel<<<(3*8*2*3*16*96 + 255)/256, 256>>>(wx);

    dim3 cgrid(64, 2, NAG);
    int gru_blocks = (NAG*64*(HW/4) + 255)/256;

    // iteration 1: src = external feats -> g_feat
    warp_mean_kernel<<<dim3(256, NAG), 256>>>(feats, trans, 0);
    conv_mma_kernel<<<cgrid, 256>>>(feats, 0);
    gru_kernel<<<gru_blocks, 256>>>(bx, bh, out, 1);

    // iteration 2: src = g_feat -> d_out
    warp_mean_kernel<<<dim3(256, NAG), 256>>>(feats, trans, 1);
    conv_mma_kernel<<<cgrid, 256>>>(feats, 1);
    gru_kernel<<<gru_blocks, 256>>>(bx, bh, out, 0);
}

// round 10
// speedup vs baseline: 2.7002x; 1.0626x over previous
#include <cuda_runtime.h>
#include <math.h>
#include <stdint.h>

#define NB 2
#define NA 5
#define NC 64
#define NH 128
#define NW 128
#define HW (NH*NW)
#define NAG (NB*NA)   /* 10 */

// Scratch (allocation-free rule: __device__ globals)
__device__ float    g_feat[NAG*NC*HW];      // 41.9 MB fp32 hidden state (warp_mean iter2 input)
__device__ uint32_t g_xin[NAG*128*HW];      // 83.9 MB tf32 conv input [n][ch128][H][W]
                                            //   ch 0..63 = feats, 64..127 = mean
__device__ float    g_yt[NAG*HW*192];       // 125.8 MB conv pre-activation [n][pix][co]
__device__ uint32_t g_wt3[48*4608];         // tf32 weights, fragment-ordered:
                                            //   region[(ky*8+cc)*2+half] x [kx][ks][wn][c3][lane32][4]

// ---------------- tf32 helpers (sm_80 ISA -> compiles at compute_103) ----------
__device__ __forceinline__ uint32_t cvt_tf32(float x) {
    uint32_t r; asm("cvt.rna.tf32.f32 %0, %1;" : "=r"(r) : "f"(x)); return r;
}
__device__ __forceinline__ void mma_tf32(float* d, const uint32_t* a,
                                         uint32_t b0, uint32_t b1) {
    asm volatile("mma.sync.aligned.m16n8k8.row.col.f32.tf32.tf32.f32 "
        "{%0,%1,%2,%3}, {%4,%5,%6,%7}, {%8,%9}, {%0,%1,%2,%3};"
        : "+f"(d[0]), "+f"(d[1]), "+f"(d[2]), "+f"(d[3])
        : "r"(a[0]), "r"(a[1]), "r"(a[2]), "r"(a[3]), "r"(b0), "r"(b1));
}
#define CP_ASYNC16(daddr, gaddr, sz) \
    asm volatile("cp.async.ca.shared.global [%0], [%1], 16, %2;" \
        :: "r"(daddr), "l"(gaddr), "r"(sz) : "memory")
#define CP_COMMIT() asm volatile("cp.async.commit_group;" ::: "memory")

// ---------------- weight prep: tf32-convert + fragment-order ----------------
__global__ void wtrans3_kernel(const float* __restrict__ wx) {
    int idx = blockIdx.x*blockDim.x + threadIdx.x;
    if (idx >= 48*4608) return;
    int r    = idx / 4608;          // region: (ky*8+cc)*2+half
    int q    = idx % 4608;
    int half = r % 2;
    int cc   = (r / 2) % 8;
    int ky   = r / 16;
    int w4   = q % 4;
    int lane = (q / 4) % 32;
    int c3   = (q / 128) % 3;
    int wn   = (q / 384) % 2;
    int ks   = (q / 768) % 2;
    int kx   = q / 1536;
    int g   = lane >> 2, tig = lane & 3;
    int w12 = c3*4 + w4;
    int nt  = w12 >> 1, h = w12 & 1;
    int co = half*96 + wn*48 + nt*8 + g;
    int ci = cc*16 + ks*8 + tig + h*4;
    g_wt3[idx] = cvt_tf32(wx[(co*128 + ci)*9 + ky*3 + kx]);
}

// ---------------- feats -> tf32 g_xin lower block (iter-1 conv input) --------
__global__ void __launch_bounds__(256) featT_kernel(const float* __restrict__ feats) {
    int t = blockIdx.x*blockDim.x + threadIdx.x;   // over NAG*64*HW/4
    if (t >= NAG*NC*HW/4) return;
    int e   = t*4;
    int pix = e & (HW - 1);
    int c   = (e >> 14) & 63;
    int n   = e >> 20;
    float4 v = *(const float4*)&feats[(n*NC + c)*HW + pix];
    uint4 o = make_uint4(cvt_tf32(v.x), cvt_tf32(v.y), cvt_tf32(v.z), cvt_tf32(v.w));
    *(uint4*)&g_xin[(n*128 + c)*HW + pix] = o;
}

// ---------------- warp + masked mean -> tf32 g_xin upper block ----------------
// 32 channels per thread (halves per-j tap math vs 16-ch version).
__global__ void __launch_bounds__(256) warp_mean_kernel(
        const float* __restrict__ ext_feats, const float* __restrict__ trans,
        int use_internal) {
    const float* feats = use_internal ? g_feat : ext_feats;
    int g   = blockIdx.x * blockDim.x + threadIdx.x;   // 0..32767
    int bi  = blockIdx.y;
    int pix = g & (HW - 1);
    int hf  = g >> 14;                                 // channel half 0/1
    int b = bi / NA, i = bi % NA;
    int h = pix >> 7, w = pix & 127;

    float acc[32];
#pragma unroll
    for (int c = 0; c < 32; c++) acc[c] = 0.f;

    for (int j = 0; j < NA; j++) {
        if (j == i) continue;
        const float* t = trans + (((b*NA + i)*NA) + j)*16;
        float t00 = t[0], t01 = t[1], t03 = t[3];
        float t10 = t[4], t11 = t[5], t13 = t[7];
        float x_tr = (4.f*t03)*(1.f/128.f);
        float y_tr = -(4.f*t13)*(1.f/128.f);
        float xsw = (float)(2*w + 1)*(1.f/128.f) - 1.f;
        float ysh = (float)(2*h + 1)*(1.f/128.f) - 1.f;
        float qx = ((xsw + x_tr + 1.f)*128.f - 1.f)*0.5f;
        float qy = ((ysh + y_tr + 1.f)*128.f - 1.f)*0.5f;
        float cx = floorf(qx), cy = floorf(qy);
        float fx = qx - cx,  fy = qy - cy;
        float w2x[2] = {1.f - fx, fx};
        float w2y[2] = {1.f - fy, fy};

        float wgt[16]; int off[16];
#pragma unroll
        for (int tt = 0; tt < 2; tt++) {
#pragma unroll
            for (int ss = 0; ss < 2; ss++) {
                float xi = cx + (float)ss, yi = cy + (float)tt;
                bool v2 = (xi >= 0.f) & (xi <= 127.f) & (yi >= 0.f) & (yi <= 127.f);
                float w2 = v2 ? w2x[ss]*w2y[tt] : 0.f;
                int q = min(max((int)xi, 0), 127);
                int p = min(max((int)yi, 0), 127);
                float xsq = (float)(2*q + 1)*(1.f/128.f) - 1.f;
                float ysp = (float)(2*p + 1)*(1.f/128.f) - 1.f;
                float gx = t00*xsq + t01*ysp;
                float gy = t10*xsq + t11*ysp;
                float px = ((gx + 1.f)*128.f - 1.f)*0.5f;
                float py = ((gy + 1.f)*128.f - 1.f)*0.5f;
                float rx = floorf(px), ry = floorf(py);
                float fx1 = px - rx, fy1 = py - ry;
                float w1x[2] = {1.f - fx1, fx1};
                float w1y[2] = {1.f - fy1, fy1};
#pragma unroll
                for (int v = 0; v < 2; v++) {
#pragma unroll
                    for (int u = 0; u < 2; u++) {
                        float xj = rx + (float)u, yj = ry + (float)v;
                        bool v1 = (xj >= 0.f) & (xj <= 127.f) & (yj >= 0.f) & (yj <= 127.f);
                        float w1 = v1 ? w1x[u]*w1y[v] : 0.f;
                        int xc = min(max((int)xj, 0), 127);
                        int yc = min(max((int)yj, 0), 127);
                        int k = (tt*2 + ss)*4 + v*2 + u;
                        wgt[k] = w2*w1;
                        off[k] = yc*NW + xc;
                    }
                }
            }
        }
        const float* fj = feats + (((b*NA + j)*NC) + hf*32)*HW;
#pragma unroll
        for (int c = 0; c < 32; c++) {
            const float* fc = fj + c*HW;
            float s = 0.f;
#pragma unroll
            for (int k = 0; k < 16; k++) s += wgt[k]*fc[off[k]];
            acc[c] += s;
        }
    }
    uint32_t* mout = g_xin + (bi*128 + 64 + hf*32)*HW + pix;
#pragma unroll
    for (int c = 0; c < 32; c++) mout[c*HW] = cvt_tf32(acc[c]*0.25f);
}

// ---------------- tf32 mma.sync conv, cp.async-pipelined ----------------
// Block = (y-pair, co-half 96, agent). M=256 (2 rows x 128 px), N=96, K=1152.
// Inputs pre-tf32 in g_xin (no cvt in hot loop); weights fragment-ordered in
// global (L1-resident, LDG.128 x3 per (kx,ks)); X double-buffered via cp.async.
#define XS_ROW 136
#define XS_RSZ (16*XS_ROW)    /* one input row: 16 ci x 136 */
#define XS_BUF (2*XS_RSZ)     /* one buffer: 2 rows */

__global__ void __launch_bounds__(256) conv_mma_kernel() {
    __shared__ uint32_t xs[2*XS_BUF];    // 34.8 KB, double-buffered

    int y0   = blockIdx.x*2;
    int half = blockIdx.y;
    int n    = blockIdx.z;
    int tid  = threadIdx.x;
    int lane = tid & 31;
    int wid  = tid >> 5;
    int g    = lane >> 2, tig = lane & 3;
    int wm   = wid & 3,  wn  = wid >> 2;
    int xbo  = (wm & 1)*64;
    int rowsel = wm >> 1;
    uint32_t xs_sh = (uint32_t)__cvta_generic_to_shared(xs);

    // x-halo zero columns (indices 3 and 132), both buffers, written once
    for (int t = tid; t < 128; t += 256) {
        int buf = t >> 6, r = t & 63;
        int ci = r & 15, hp = (r >> 4) & 1, row = r >> 5;
        xs[buf*XS_BUF + row*XS_RSZ + ci*XS_ROW + (hp ? 132 : 3)] = 0;
    }

    float acc[4][6][4];
#pragma unroll
    for (int mt = 0; mt < 4; mt++)
#pragma unroll
        for (int nt = 0; nt < 6; nt++)
#pragma unroll
            for (int q = 0; q < 4; q++) acc[mt][nt][q] = 0.f;

    // stage chunk k into buffer buf (4 cp.async of 16B per thread)
    auto stage = [&](int k, int buf) {
        int ky = k >> 3, cc = k & 7;
#pragma unroll
        for (int ff = 0; ff < 4; ff++) {
            int f = tid + ff*256;
            int xg = f & 31, ci = (f >> 5) & 15, row = f >> 9;
            int gy = y0 - 1 + ky + row;
            unsigned sz = ((unsigned)gy < 128u) ? 16u : 0u;
            int gyc = min(max(gy, 0), 127);
            const uint32_t* src = g_xin + ((n*128 + cc*16 + ci)*NH + gyc)*NW + xg*4;
            uint32_t daddr = xs_sh +
                (buf*XS_BUF + row*XS_RSZ + ci*XS_ROW + xg*4 + 4)*4;
            CP_ASYNC16(daddr, src, sz);
        }
        CP_COMMIT();
    };

    stage(0, 0);

    for (int k = 0; k < 24; k++) {
        int b  = k & 1;
        int ky = k >> 3, cc = k & 7;
        if (k) __syncthreads();                       // protect buf being restaged
        if (k + 1 < 24) stage(k + 1, (k + 1) & 1);
        if (k + 1 < 24) asm volatile("cp.async.wait_group 1;" ::: "memory");
        else            asm volatile("cp.async.wait_group 0;" ::: "memory");
        __syncthreads();                              // staged data visible to all

        const uint32_t* xbuf = xs + b*XS_BUF + rowsel*XS_RSZ;
        const uint32_t* wreg = g_wt3 + ((ky*8 + cc)*2 + half)*4608;
#pragma unroll
        for (int ks = 0; ks < 2; ks++) {
            const uint32_t* arow = xbuf + (ks*8 + tig)*XS_ROW;
#pragma unroll
            for (int kx = 0; kx < 3; kx++) {
                const uint4* wp = (const uint4*)(wreg +
                    ((((kx*2 + ks)*2 + wn)*3)*32 + lane)*4);
                uint4 b0 = wp[0];
                uint4 b1 = wp[32];
                uint4 b2 = wp[64];
                uint32_t A[4][4];
#pragma unroll
                for (int mt = 0; mt < 4; mt++) {
                    int xi = xbo + mt*16 + g + kx + 3;
                    A[mt][0] = arow[xi];
                    A[mt][1] = arow[xi + 8];
                    A[mt][2] = arow[xi + 4*XS_ROW];
                    A[mt][3] = arow[xi + 8 + 4*XS_ROW];
                }
#pragma unroll
                for (int mt = 0; mt < 4; mt++) {
                    mma_tf32(acc[mt][0], A[mt], b0.x, b0.y);
                    mma_tf32(acc[mt][1], A[mt], b0.z, b0.w);
                    mma_tf32(acc[mt][2], A[mt], b1.x, b1.y);
                    mma_tf32(acc[mt][3], A[mt], b1.z, b1.w);
                    mma_tf32(acc[mt][4], A[mt], b2.x, b2.y);
                    mma_tf32(acc[mt][5], A[mt], b2.z, b2.w);
                }
            }
        }
    }

    // epilogue: D frag rows (g, g+8), cols (2tig, 2tig+1) -> g_yt [n][pix][co]
    int yy = y0 + rowsel;
#pragma unroll
    for (int mt = 0; mt < 4; mt++) {
        int x = xbo + mt*16 + g;
#pragma unroll
        for (int nt = 0; nt < 6; nt++) {
            int cobase = half*96 + wn*48 + nt*8 + tig*2;
            float* p0 = &g_yt[(size_t)(n*HW + yy*NW + x)*192 + cobase];
            *(float2*)p0 = make_float2(acc[mt][nt][0], acc[mt][nt][1]);
            float* p1 = p0 + 8*192;
            *(float2*)p1 = make_float2(acc[mt][nt][2], acc[mt][nt][3]);
        }
    }
}

// ---------------- fused GRU epilogue (h0 = 0) ----------------
// iter1 (to_internal): writes fp32 g_feat + tf32 g_xin lower block
// iter2: writes fp32 d_out
__global__ void __launch_bounds__(256) gru_kernel(
        const float* __restrict__ bx, const float* __restrict__ bh,
        float* __restrict__ ext_out, int to_internal) {
    int t = blockIdx.x*blockDim.x + threadIdx.x;   // over NAG*64*(HW/4)
    if (t >= NAG*64*(HW/4)) return;
    int c  = t & 63;
    int pg = (t >> 6) & (HW/4 - 1);
    int n  = t >> 18;
    int pix = pg*4;
    float br  = bx[c] + bh[c];
    float bz  = bx[64 + c] + bh[64 + c];
    float bxn = bx[128 + c], bhn = bh[128 + c];
    const float* yb = g_yt + (size_t)(n*HW + pix)*192;
    float o[4];
#pragma unroll
    for (int p = 0; p < 4; p++) {
        float yr = yb[p*192 + c];
        float yz = yb[p*192 + 64 + c];
        float yn = yb[p*192 + 128 + c];
        float r = 1.f/(1.f + __expf(-(yr + br)));
        float z = 1.f/(1.f + __expf(-(yz + bz)));
        o[p] = (1.f - z)*tanhf(yn + bxn + r*bhn);
    }
    float4 of = make_float4(o[0], o[1], o[2], o[3]);
    if (to_internal) {
        *(float4*)&g_feat[(n*NC + c)*HW + pix] = of;
        uint4 ot = make_uint4(cvt_tf32(o[0]), cvt_tf32(o[1]),
                              cvt_tf32(o[2]), cvt_tf32(o[3]));
        *(uint4*)&g_xin[(n*128 + c)*HW + pix] = ot;
    } else {
        *(float4*)&ext_out[(n*NC + c)*HW + pix] = of;
    }
}

// ---------------- launch ----------------
extern "C" void kernel_launch(void* const* d_in, const int* in_sizes, int n_in,
                              void* d_out, int out_size) {
    const float* feats = (const float*)d_in[0];
    const float* trans = (const float*)d_in[1];
    const float* wx    = (const float*)d_in[2];
    const float* bx    = (const float*)d_in[4];
    const float* bh    = (const float*)d_in[5];
    float* out = (float*)d_out;

    wtrans3_kernel<<<(48*4608 + 255)/256, 256>>>(wx);
    featT_kernel<<<(NAG*NC*HW/4 + 255)/256, 256>>>(feats);

    dim3 cgrid(64, 2, NAG);
    int gru_blocks = (NAG*64*(HW/4) + 255)/256;

    // iteration 1: src = external feats
    warp_mean_kernel<<<dim3(128, NAG), 256>>>(feats, trans, 0);
    conv_mma_kernel<<<cgrid, 256>>>();
    gru_kernel<<<gru_blocks, 256>>>(bx, bh, out, 1);

    // iteration 2: src = internal state
    warp_mean_kernel<<<dim3(128, NAG), 256>>>(feats, trans, 1);
    conv_mma_kernel<<<cgrid, 256>>>();
    gru_kernel<<<gru_blocks, 256>>>(bx, bh, out, 0);
}